// round 14
// baseline (speedup 1.0000x reference)
#include <cuda_runtime.h>
#include <cuda_fp16.h>
#include <cstdint>
#include <cstddef>

// ---------------------------------------------------------------------------
// GATDecoder round 14: R13 + ldmatrix (LDSM.x4) fragment loads in the GEMM
// mainloop (4 LDSM per k-step instead of 16 scalar LDS). Everything else
// identical to the passing R13 build.
// ---------------------------------------------------------------------------

#define MAX_N 50000
#define MAX_E 800000
#define MAX_EDGES_SL (MAX_E + MAX_N)

__device__ __align__(256) __half g_h16a[MAX_N * 256];
__device__ __align__(256) __half g_h16b[MAX_N * 256];
__device__ __align__(256) __half g_aprim16[MAX_N * 64];
__device__ __align__(256) __half g_wt[139264];   // all weights, fp16, [Nd][K]
__device__ float g_ws[384];    // W@a_src: L2 [0,64), L3 [64,192), L4 [192,384)
__device__ float g_wd[384];
__device__ float g_ssrc[MAX_N];
__device__ float g_sdst[MAX_N];
__device__ float g_ssrc2[MAX_N];
__device__ float g_sdst2[MAX_N];
__device__ int   g_counts[MAX_N];
__device__ int   g_rowptr[MAX_N + 1];
__device__ int   g_off[MAX_N];
__device__ int   g_colsrc[MAX_EDGES_SL];
__device__ int   g_src[MAX_E];
__device__ int   g_dst[MAX_E];
__device__ int   g_blocksum[64];
__device__ int   g_flag64;

// wt arena offsets (halves). WTZ and WTA contiguous -> merged head GEMM.
#define WT1_OFF 0
#define WT2_OFF 8192
#define WT3_OFF 16384
#define WT4_OFF 40960
#define WTZ_OFF 90112
#define WTA_OFF 122880

// ---------------------------------------------------------------------------
__global__ void detect_dtype_kernel(const int* __restrict__ ei32)
{
    __shared__ int s_any;
    int tid = threadIdx.x;
    if (tid == 0) s_any = 0;
    __syncthreads();
    int any = 0;
    for (int i = tid; i < 1024; i += blockDim.x)
        any |= ei32[2 * i + 1];
    if (any) atomicOr(&s_any, 1);
    __syncthreads();
    if (tid == 0) g_flag64 = (s_any == 0) ? 1 : 0;
}

// fused: z->fp16 + 6 weight transposes + counts init
__global__ void setup_kernel(const float* __restrict__ z,
                             const float* __restrict__ W1, const float* __restrict__ W2,
                             const float* __restrict__ W3, const float* __restrict__ W4,
                             const float* __restrict__ Wz, const float* __restrict__ Wa,
                             __half* __restrict__ hb, __half* __restrict__ wt, int N)
{
    int idx = blockIdx.x * blockDim.x + threadIdx.x;
    int A = N * 32;                      // float4 items of z
    if (idx < A) {
        int i = idx * 4;
        float4 v = *reinterpret_cast<const float4*>(z + i);
        __half2 h0 = __floats2half2_rn(v.x, v.y);
        __half2 h1 = __floats2half2_rn(v.z, v.w);
        uint2 packed;
        packed.x = *reinterpret_cast<uint32_t*>(&h0);
        packed.y = *reinterpret_cast<uint32_t*>(&h1);
        *reinterpret_cast<uint2*>(hb + i) = packed;
        return;
    }
    int j = idx - A;
    const float* W; int K, Nd, off, jl;
    if (j < 8192)        { W = W1; K = 128; Nd = 64;  off = WT1_OFF; jl = j; }
    else if (j < 16384)  { W = W2; K = 64;  Nd = 128; off = WT2_OFF; jl = j - 8192; }
    else if (j < 40960)  { W = W3; K = 128; Nd = 192; off = WT3_OFF; jl = j - 16384; }
    else if (j < 90112)  { W = W4; K = 192; Nd = 256; off = WT4_OFF; jl = j - 40960; }
    else if (j < 122880) { W = Wz; K = 256; Nd = 128; off = WTZ_OFF; jl = j - 90112; }
    else if (j < 139264) { W = Wa; K = 256; Nd = 64;  off = WTA_OFF; jl = j - 122880; }
    else {
        int n = j - 139264;
        if (n < N) g_counts[n] = 1;      // self loop
        return;
    }
    int k = jl / Nd, n = jl % Nd;
    wt[off + n * K + k] = __float2half(W[jl]);
}

__global__ void convert_hist_kernel(const void* __restrict__ ei, int E)
{
    int e = blockIdx.x * blockDim.x + threadIdx.x;
    if (e >= E) return;
    int s, d;
    if (g_flag64) {
        const long long* p = (const long long*)ei;
        s = (int)p[e];
        d = (int)p[E + e];
    } else {
        const int* p = (const int*)ei;
        s = p[e];
        d = p[E + e];
    }
    g_src[e] = s;
    g_dst[e] = d;
    atomicAdd(&g_counts[d], 1);
}

// --- parallel 3-phase exclusive scan ---
__global__ void scan1_kernel(int N)
{
    __shared__ int wsum[32];
    int blk = blockIdx.x;
    int tid = threadIdx.x;
    int lane = tid & 31, wid = tid >> 5;
    int i = blk * 1024 + tid;
    int v = (i < N) ? g_counts[i] : 0;
    int x = v;
    #pragma unroll
    for (int o = 1; o < 32; o <<= 1) {
        int t = __shfl_up_sync(0xffffffffu, x, o);
        if (lane >= o) x += t;
    }
    if (lane == 31) wsum[wid] = x;
    __syncthreads();
    if (wid == 0) {
        int y = wsum[lane];
        #pragma unroll
        for (int o = 1; o < 32; o <<= 1) {
            int t = __shfl_up_sync(0xffffffffu, y, o);
            if (lane >= o) y += t;
        }
        wsum[lane] = y;
    }
    __syncthreads();
    int add = (wid > 0) ? wsum[wid - 1] : 0;
    if (i < N) g_rowptr[i] = x + add - v;
    if (tid == 0) g_blocksum[blk] = wsum[31];
}

__global__ void scan2_kernel(int nblk, int N)
{
    __shared__ int s[64];
    int tid = threadIdx.x;
    int v = (tid < nblk) ? g_blocksum[tid] : 0;
    s[tid] = v;
    __syncthreads();
    #pragma unroll
    for (int off = 1; off < 64; off <<= 1) {
        int t = (tid >= off) ? s[tid - off] : 0;
        __syncthreads();
        s[tid] += t;
        __syncthreads();
    }
    g_blocksum[tid] = s[tid] - v;
    if (tid == nblk - 1) g_rowptr[N] = s[tid];
}

__global__ void scan3_fill_kernel(int N)
{
    int i = blockIdx.x * blockDim.x + threadIdx.x;
    if (i >= N) return;
    int p = g_rowptr[i] + g_blocksum[i >> 10];
    g_rowptr[i] = p;
    g_colsrc[p] = i;
    g_off[i] = p + 1;
}

__global__ void scatter_kernel(int E)
{
    int e = blockIdx.x * blockDim.x + threadIdx.x;
    if (e >= E) return;
    int d = g_dst[e];
    int pos = atomicAdd(&g_off[d], 1);
    g_colsrc[pos] = g_src[e];
}

// ---------------------------------------------------------------------------
// cp.async helpers
// ---------------------------------------------------------------------------
__device__ __forceinline__ void cp_async16(void* smem, const void* gmem)
{
    uint32_t saddr = (uint32_t)__cvta_generic_to_shared(smem);
    asm volatile("cp.async.cg.shared.global [%0], [%1], 16;\n"
                 :: "r"(saddr), "l"(gmem));
}
__device__ __forceinline__ void cp_commit()
{
    asm volatile("cp.async.commit_group;\n");
}
template<int NN>
__device__ __forceinline__ void cp_wait()
{
    asm volatile("cp.async.wait_group %0;\n" :: "n"(NN));
}

// ---------------------------------------------------------------------------
// fp16 tensor-core GEMM, 3-stage cp.async, BM=128 BN=64 BK=32, LDSM frags.
// 256 thr = 8 warps (4Mx2N), 32x32 per warp. mma m16n8k16, fp32 accum.
// Split-head mode: bn >= split goes to C2 (fp16, ld = Nd-split) with bias2.
// ---------------------------------------------------------------------------
#define SSTR 40

__device__ __forceinline__ void mma_f16(float c[4], const uint32_t a[4], const uint32_t b[2])
{
    asm volatile(
        "mma.sync.aligned.m16n8k16.row.col.f32.f16.f16.f32 "
        "{%0,%1,%2,%3}, {%4,%5,%6,%7}, {%8,%9}, {%0,%1,%2,%3};"
        : "+f"(c[0]), "+f"(c[1]), "+f"(c[2]), "+f"(c[3])
        : "r"(a[0]), "r"(a[1]), "r"(a[2]), "r"(a[3]), "r"(b[0]), "r"(b[1]));
}

__device__ __forceinline__ void ldsm4(uint32_t r[4], uint32_t addr)
{
    asm volatile(
        "ldmatrix.sync.aligned.m8n8.x4.shared.b16 {%0,%1,%2,%3}, [%4];"
        : "=r"(r[0]), "=r"(r[1]), "=r"(r[2]), "=r"(r[3]) : "r"(addr));
}

__device__ __forceinline__ float lrelu(float x, float s) { return x > 0.f ? x : s * x; }

__device__ __forceinline__ void store2(float* p, float a, float b)
{
    *reinterpret_cast<float2*>(p) = make_float2(a, b);
}
__device__ __forceinline__ void store2(__half* p, float a, float b)
{
    *reinterpret_cast<__half2*>(p) = __floats2half2_rn(a, b);
}

template<typename TC>
__global__ __launch_bounds__(256) void gemm_fp16_kernel(
    const __half* __restrict__ A, const __half* __restrict__ WT,
    const float* __restrict__ bias, TC* __restrict__ C,
    int M, int K, int Nd, int act, int cld,
    const float* __restrict__ bias2, __half* __restrict__ C2, int split)
{
    __shared__ __half As[3][128 * SSTR];
    __shared__ __half Bs[3][64 * SSTR];

    int bm = blockIdx.y * 128;
    int bn = blockIdx.x * 64;
    int tid = threadIdx.x;
    int warp = tid >> 5;
    int lane = tid & 31;
    int g = lane >> 2;
    int t = lane & 3;
    int warpM = warp >> 1;
    int warpN = warp & 1;

    int arow0 = tid >> 2;
    int arow1 = arow0 + 64;
    int aq = (tid & 3) << 3;
    int ag0 = (bm + arow0 < M) ? (bm + arow0) : (M - 1);
    int ag1 = (bm + arow1 < M) ? (bm + arow1) : (M - 1);
    int brow = tid >> 2;
    int bq = aq;

    const __half* Bg = WT + (size_t)(bn + brow) * K + bq;
    const __half* Ag0 = A + (size_t)ag0 * K + aq;
    const __half* Ag1 = A + (size_t)ag1 * K + aq;

    // LDSM lane offsets (in bytes, relative to tile base)
    //  A x4 (m16k16): lanes 0-15 -> rows, lanes 16-31 -> rows with k+8
    uint32_t offA = (uint32_t)(((warpM * 32 + (lane & 15)) * SSTR + ((lane >> 4) << 3)) << 1);
    //  B x4 (n32k16): all 32 lanes -> n rows
    uint32_t offB = (uint32_t)(((warpN * 32 + lane) * SSTR) << 1);

    uint32_t asb[3], bsb[3];
    #pragma unroll
    for (int i = 0; i < 3; i++) {
        asb[i] = (uint32_t)__cvta_generic_to_shared(As[i]);
        bsb[i] = (uint32_t)__cvta_generic_to_shared(Bs[i]);
    }

    float acc[2][4][4];
    #pragma unroll
    for (int mf = 0; mf < 2; mf++)
        #pragma unroll
        for (int nf = 0; nf < 4; nf++)
            #pragma unroll
            for (int i = 0; i < 4; i++) acc[mf][nf][i] = 0.f;

    int iters = K >> 5;

    cp_async16(As[0] + arow0 * SSTR + aq, Ag0);
    cp_async16(As[0] + arow1 * SSTR + aq, Ag1);
    cp_async16(Bs[0] + brow * SSTR + bq, Bg);
    cp_commit();
    if (iters > 1) {
        cp_async16(As[1] + arow0 * SSTR + aq, Ag0 + 32);
        cp_async16(As[1] + arow1 * SSTR + aq, Ag1 + 32);
        cp_async16(Bs[1] + brow * SSTR + bq, Bg + 32);
    }
    cp_commit();

    int buf = 0;
    for (int it = 0; it < iters; it++) {
        int pre = it + 2;
        if (pre < iters) {
            int nb = pre - (pre / 3) * 3;
            int off = pre << 5;
            cp_async16(As[nb] + arow0 * SSTR + aq, Ag0 + off);
            cp_async16(As[nb] + arow1 * SSTR + aq, Ag1 + off);
            cp_async16(Bs[nb] + brow * SSTR + bq, Bg + off);
        }
        cp_commit();
        cp_wait<2>();
        __syncthreads();

        uint32_t ab = asb[buf];
        uint32_t bb = bsb[buf];
        #pragma unroll
        for (int kk = 0; kk < 32; kk += 16) {
            uint32_t a0[4], a1[4], b0[4], b1[4];
            ldsm4(a0, ab + offA + (kk << 1));                        // mf=0
            ldsm4(a1, ab + offA + ((16 * SSTR + kk) << 1));          // mf=1
            ldsm4(b0, bb + offB + (kk << 1));                        // k lo
            ldsm4(b1, bb + offB + ((kk + 8) << 1));                  // k hi
            #pragma unroll
            for (int nf = 0; nf < 4; nf++) {
                uint32_t bfrag[2] = {b0[nf], b1[nf]};
                mma_f16(acc[0][nf], a0, bfrag);
                mma_f16(acc[1][nf], a1, bfrag);
            }
        }
        __syncthreads();
        buf++;
        if (buf == 3) buf = 0;
    }

    if (bn < split) {
        #pragma unroll
        for (int mf = 0; mf < 2; mf++) {
            int r0 = bm + warpM * 32 + mf * 16 + g;
            #pragma unroll
            for (int nf = 0; nf < 4; nf++) {
                int col = bn + warpN * 32 + nf * 8 + t * 2;
                float bx = 0.f, by = 0.f;
                if (bias) { bx = bias[col]; by = bias[col + 1]; }
                float v0 = acc[mf][nf][0] + bx, v1 = acc[mf][nf][1] + by;
                float v2 = acc[mf][nf][2] + bx, v3 = acc[mf][nf][3] + by;
                if (act) {
                    v0 = lrelu(v0, 0.01f); v1 = lrelu(v1, 0.01f);
                    v2 = lrelu(v2, 0.01f); v3 = lrelu(v3, 0.01f);
                }
                if (r0 < M)
                    store2(C + (size_t)r0 * cld + col, v0, v1);
                if (r0 + 8 < M)
                    store2(C + (size_t)(r0 + 8) * cld + col, v2, v3);
            }
        }
    } else {
        int ld2 = Nd - split;
        #pragma unroll
        for (int mf = 0; mf < 2; mf++) {
            int r0 = bm + warpM * 32 + mf * 16 + g;
            #pragma unroll
            for (int nf = 0; nf < 4; nf++) {
                int col = bn + warpN * 32 + nf * 8 + t * 2 - split;
                float bx = bias2[col], by = bias2[col + 1];
                float v0 = acc[mf][nf][0] + bx, v1 = acc[mf][nf][1] + by;
                float v2 = acc[mf][nf][2] + bx, v3 = acc[mf][nf][3] + by;
                if (r0 < M)
                    store2(C2 + (size_t)r0 * ld2 + col, v0, v1);
                if (r0 + 8 < M)
                    store2(C2 + (size_t)(r0 + 8) * ld2 + col, v2, v3);
            }
        }
    }
}

// ---------------------------------------------------------------------------
// wvec for layers 2-4 in one launch: g_ws/g_wd[base+k] = W[k,:] . a
// ---------------------------------------------------------------------------
__global__ void wvec_all_kernel(const float* __restrict__ W2, const float* __restrict__ W3,
                                const float* __restrict__ W4,
                                const float* __restrict__ as2, const float* __restrict__ ad2,
                                const float* __restrict__ as3, const float* __restrict__ ad3,
                                const float* __restrict__ as4, const float* __restrict__ ad4)
{
    int w = (blockIdx.x * blockDim.x + threadIdx.x) >> 5;
    int lane = threadIdx.x & 31;
    if (w >= 384) return;
    const float* W; const float* as; const float* ad; int Do, base, k;
    if (w < 64)       { W = W2; as = as2; ad = ad2; Do = 128; base = 0;   k = w; }
    else if (w < 192) { W = W3; as = as3; ad = ad3; Do = 192; base = 64;  k = w - 64; }
    else              { W = W4; as = as4; ad = ad4; Do = 256; base = 192; k = w - 192; }
    const float* wr = W + (size_t)k * Do;
    float s1 = 0.f, s2 = 0.f;
    for (int d = lane; d < Do; d += 32) {
        float v = wr[d];
        s1 += v * as[d];
        s2 += v * ad[d];
    }
    #pragma unroll
    for (int o = 16; o > 0; o >>= 1) {
        s1 += __shfl_xor_sync(0xffffffffu, s1, o);
        s2 += __shfl_xor_sync(0xffffffffu, s2, o);
    }
    if (lane == 0) {
        g_ws[base + k] = s1;
        g_wd[base + k] = s2;
    }
}

// ---------------------------------------------------------------------------
__device__ __forceinline__ void unpack8(int4 raw, float f[8])
{
    const __half2* hp = reinterpret_cast<const __half2*>(&raw);
    #pragma unroll
    for (int r = 0; r < 4; r++) {
        float2 v = __half22float2(hp[r]);
        f[2 * r] = v.x;
        f[2 * r + 1] = v.y;
    }
}

// ---------------------------------------------------------------------------
// dots: 8-lane groups, 4 nodes per warp, int4 loads. writes (o1, o2).
// ---------------------------------------------------------------------------
template<int D>
__global__ void dots_kernel(const __half* __restrict__ x,
                            const float* __restrict__ v1,
                            const float* __restrict__ v2,
                            float* __restrict__ o1,
                            float* __restrict__ o2,
                            int N)
{
    constexpr int V = D / 8;
    constexpr int NI4 = V / 8;
    int warp = (blockIdx.x * blockDim.x + threadIdx.x) >> 5;
    int lane = threadIdx.x & 31;
    int grp = lane >> 3, gl = lane & 7;
    int node = warp * 4 + grp;
    bool valid = node < N;

    float s1 = 0.f, s2 = 0.f;
    if (valid) {
        const int4* xr = reinterpret_cast<const int4*>(x + (size_t)node * D + gl * V);
        #pragma unroll
        for (int q = 0; q < NI4; q++) {
            float f[8];
            unpack8(xr[q], f);
            int d0 = gl * V + q * 8;
            #pragma unroll
            for (int r = 0; r < 8; r++) {
                s1 += f[r] * v1[d0 + r];
                s2 += f[r] * v2[d0 + r];
            }
        }
    }
    #pragma unroll
    for (int o = 4; o > 0; o >>= 1) {
        s1 += __shfl_xor_sync(0xffffffffu, s1, o);
        s2 += __shfl_xor_sync(0xffffffffu, s2, o);
    }
    if (valid && gl == 0) {
        o1[node] = s1;
        o2[node] = s2;
    }
}

// ---------------------------------------------------------------------------
// Aggregate: warp per node, 4 edge-groups of 8 lanes, online softmax per
// group, shuffle merge. Prefetch of next edge's (colsrc, ssrc) breaks the
// dependent-load chain. Optional fused dot of OUTPUT row -> (dout1, dout2).
// ---------------------------------------------------------------------------
template<int D>
__global__ void aggregate_kernel(const __half* __restrict__ feat,
                                 const float* __restrict__ bias,
                                 __half* __restrict__ out,
                                 int N, int act,
                                 const float* __restrict__ ssrc,
                                 const float* __restrict__ sdst,
                                 const float* __restrict__ dv1,
                                 const float* __restrict__ dv2,
                                 float* __restrict__ dout1,
                                 float* __restrict__ dout2)
{
    constexpr int V = D / 8;
    constexpr int NI4 = V / 8;
    int warp = (blockIdx.x * blockDim.x + threadIdx.x) >> 5;
    int lane = threadIdx.x & 31;
    int grp = lane >> 3, gl = lane & 7;
    if (warp >= N) return;
    int beg = g_rowptr[warp];
    int end = g_rowptr[warp + 1];
    float sd = sdst[warp];

    float m = -1e30f;
    float s = 0.f;
    float acc[V];
    #pragma unroll
    for (int v = 0; v < V; v++) acc[v] = 0.f;

    // software pipeline: src and its score fetched one iteration early
    int j = beg + grp;
    int src = 0;
    float sv = 0.f;
    if (j < end) {
        src = g_colsrc[j];
        sv = ssrc[src];
    }
    while (j < end) {
        int jn = j + 4;
        int srcn = 0;
        float svn = 0.f;
        if (jn < end) {
            srcn = g_colsrc[jn];
            svn = ssrc[srcn];
        }
        float a = lrelu(sv + sd, 0.2f);
        if (a > m) {
            float f = __expf(m - a);
            s *= f;
            #pragma unroll
            for (int v = 0; v < V; v++) acc[v] *= f;
            m = a;
        }
        float w = __expf(a - m);
        s += w;
        const int4* fr = reinterpret_cast<const int4*>(feat + (size_t)src * D + gl * V);
        #pragma unroll
        for (int q = 0; q < NI4; q++) {
            float f[8];
            unpack8(fr[q], f);
            #pragma unroll
            for (int r = 0; r < 8; r++)
                acc[q * 8 + r] += w * f[r];
        }
        j = jn;
        src = srcn;
        sv = svn;
    }

    // merge the 4 groups (xor butterfly over strides 8, 16)
    #pragma unroll
    for (int off = 8; off <= 16; off <<= 1) {
        float m2 = __shfl_xor_sync(0xffffffffu, m, off);
        float s2 = __shfl_xor_sync(0xffffffffu, s, off);
        float mn = fmaxf(m, m2);
        float f1 = __expf(m - mn);
        float f2 = __expf(m2 - mn);
        s = s * f1 + s2 * f2;
        #pragma unroll
        for (int v = 0; v < V; v++) {
            float o = __shfl_xor_sync(0xffffffffu, acc[v], off);
            acc[v] = acc[v] * f1 + o * f2;
        }
        m = mn;
    }

    float inv = 1.f / (s + 1e-16f);
    float d1 = 0.f, d2 = 0.f;
    if (grp == 0) {
        __half* orow = out + (size_t)warp * D + gl * V;
        #pragma unroll
        for (int q = 0; q < NI4; q++) {
            int4 raw;
            __half2* hp = reinterpret_cast<__half2*>(&raw);
            #pragma unroll
            for (int r = 0; r < 4; r++) {
                int d = gl * V + q * 8 + 2 * r;
                float v0 = acc[q * 8 + 2 * r] * inv;
                float v1 = acc[q * 8 + 2 * r + 1] * inv;
                if (bias) { v0 += bias[d]; v1 += bias[d + 1]; }
                if (act) { v0 = lrelu(v0, 0.01f); v1 = lrelu(v1, 0.01f); }
                hp[r] = __floats2half2_rn(v0, v1);
                if (dv1) {
                    d1 += v0 * dv1[d] + v1 * dv1[d + 1];
                    d2 += v0 * dv2[d] + v1 * dv2[d + 1];
                }
            }
            *reinterpret_cast<int4*>(orow + q * 8) = raw;
        }
    }
    if (dv1) {
        #pragma unroll
        for (int o = 4; o > 0; o >>= 1) {
            d1 += __shfl_xor_sync(0xffffffffu, d1, o);
            d2 += __shfl_xor_sync(0xffffffffu, d2, o);
        }
        if (grp == 0 && gl == 0) {
            dout1[warp] = d1;
            dout2[warp] = d2;
        }
    }
}

// ---------------------------------------------------------------------------
// inner: 8-lane groups, 4 edges per warp, int4 loads (D=64).
// ---------------------------------------------------------------------------
__global__ void inner_kernel(float* __restrict__ out, int E)
{
    int warp = (blockIdx.x * blockDim.x + threadIdx.x) >> 5;
    int lane = threadIdx.x & 31;
    int grp = lane >> 3, gl = lane & 7;
    int e = warp * 4 + grp;
    bool valid = e < E;

    float acc = 0.f;
    if (valid) {
        int s = g_src[e];
        int d = g_dst[e];
        int4 a4 = *reinterpret_cast<const int4*>(g_aprim16 + (size_t)s * 64 + gl * 8);
        int4 b4 = *reinterpret_cast<const int4*>(g_aprim16 + (size_t)d * 64 + gl * 8);
        float fa[8], fb[8];
        unpack8(a4, fa);
        unpack8(b4, fb);
        #pragma unroll
        for (int r = 0; r < 8; r++)
            acc += fa[r] * fb[r];
    }
    #pragma unroll
    for (int o = 4; o > 0; o >>= 1)
        acc += __shfl_xor_sync(0xffffffffu, acc, o);
    if (valid && gl == 0)
        out[e] = 1.f / (1.f + expf(-acc));
}

// ---------------------------------------------------------------------------
static void launch_aggregate(const __half* feat, const float* bias, __half* out,
                             int N, int D, int act,
                             const float* ssrc, const float* sdst,
                             const float* dv1, const float* dv2,
                             float* dout1, float* dout2,
                             int wgrid, int TB)
{
    switch (D) {
        case 64:  aggregate_kernel<64> <<<wgrid, TB>>>(feat, bias, out, N, act, ssrc, sdst, dv1, dv2, dout1, dout2); break;
        case 128: aggregate_kernel<128><<<wgrid, TB>>>(feat, bias, out, N, act, ssrc, sdst, dv1, dv2, dout1, dout2); break;
        case 192: aggregate_kernel<192><<<wgrid, TB>>>(feat, bias, out, N, act, ssrc, sdst, dv1, dv2, dout1, dout2); break;
        default:  break;
    }
}

static void launch_dots(const __half* x, const float* v1, const float* v2,
                        float* o1, float* o2, int N, int D, int TB)
{
    int grid = (((N + 3) / 4) * 32 + TB - 1) / TB;
    switch (D) {
        case 64:  dots_kernel<64> <<<grid, TB>>>(x, v1, v2, o1, o2, N); break;
        case 128: dots_kernel<128><<<grid, TB>>>(x, v1, v2, o1, o2, N); break;
        case 192: dots_kernel<192><<<grid, TB>>>(x, v1, v2, o1, o2, N); break;
        default:  break;
    }
}

extern "C" void kernel_launch(void* const* d_in, const int* in_sizes, int n_in,
                              void* d_out, int out_size)
{
    const float* z   = (const float*)d_in[0];
    const void*  ei  = d_in[1];
    const float* W1  = (const float*)d_in[2];
    const float* as1 = (const float*)d_in[3];
    const float* ad1 = (const float*)d_in[4];
    const float* b1  = (const float*)d_in[5];
    const float* W2  = (const float*)d_in[6];
    const float* as2 = (const float*)d_in[7];
    const float* ad2 = (const float*)d_in[8];
    const float* b2  = (const float*)d_in[9];
    const float* W3  = (const float*)d_in[10];
    const float* as3 = (const float*)d_in[11];
    const float* ad3 = (const float*)d_in[12];
    const float* b3  = (const float*)d_in[13];
    const float* W4  = (const float*)d_in[14];
    const float* as4 = (const float*)d_in[15];
    const float* ad4 = (const float*)d_in[16];
    const float* b4  = (const float*)d_in[17];
    const float* Wz  = (const float*)d_in[18];
    const float* bz  = (const float*)d_in[19];
    const float* Wa  = (const float*)d_in[20];
    const float* ba  = (const float*)d_in[21];

    int N = in_sizes[0] / 128;
    if (N > MAX_N) N = MAX_N;
    int E = in_sizes[1] / 2;
    if (E > MAX_E) E = MAX_E;

    float* out_z     = (float*)d_out;
    float* out_inner = (float*)d_out + (size_t)N * 128;

    __half* ha;  cudaGetSymbolAddress((void**)&ha, g_h16a);
    __half* hb;  cudaGetSymbolAddress((void**)&hb, g_h16b);
    __half* ap;  cudaGetSymbolAddress((void**)&ap, g_aprim16);
    __half* wt;  cudaGetSymbolAddress((void**)&wt, g_wt);
    float* ws;   cudaGetSymbolAddress((void**)&ws, g_ws);
    float* wd;   cudaGetSymbolAddress((void**)&wd, g_wd);
    float* s1;   cudaGetSymbolAddress((void**)&s1, g_ssrc);
    float* sd1;  cudaGetSymbolAddress((void**)&sd1, g_sdst);
    float* s2;   cudaGetSymbolAddress((void**)&s2, g_ssrc2);
    float* sd2;  cudaGetSymbolAddress((void**)&sd2, g_sdst2);

    const int TB = 256;
    int egrid = (E + TB - 1) / TB;
    int ngrid = (N + TB - 1) / TB;
    int wgrid = (N * 32 + TB - 1) / TB;               // warp-per-node
    int iegrid = (((E + 3) / 4) * 32 + TB - 1) / TB;  // 4 edges per warp
    int nblk = (N + 1023) / 1024;
    int setup_items = N * 32 + 139264 + N;
    int sgrid = (setup_items + TB - 1) / TB;
    int mt = (N + 127) / 128;                         // 128-row M tiles
    const int NS = 1 << 30;                           // "no split"

    // 1: dtype detect; 2: fused setup; 3: edge convert + histogram
    detect_dtype_kernel<<<1, 256>>>((const int*)ei);
    setup_kernel<<<sgrid, TB>>>(z, W1, W2, W3, W4, Wz, Wa, hb, wt, N);
    convert_hist_kernel<<<egrid, TB>>>(ei, E);
    // 4: L1 GEMM: hb (z16) -> ha
    {
        dim3 grid(1, mt);
        gemm_fp16_kernel<__half><<<grid, 256>>>(hb, wt + WT1_OFF, nullptr, ha,
                                                N, 128, 64, 0, 64, nullptr, nullptr, NS);
    }
    // 5: dots for layer 1; 6: wvec for layers 2-4
    launch_dots(ha, as1, ad1, s1, sd1, N, 64, TB);
    wvec_all_kernel<<<48, TB>>>(W2, W3, W4, as2, ad2, as3, ad3, as4, ad4);
    // 7-10: CSR build
    scan1_kernel<<<nblk, 1024>>>(N);
    scan2_kernel<<<1, 64>>>(nblk, N);
    scan3_fill_kernel<<<ngrid, TB>>>(N);
    scatter_kernel<<<egrid, TB>>>(E);

    // Layer 1 aggregate (D=64): ha -> hb; scores buf1, fused L2 dots -> buf2
    launch_aggregate(ha, b1, hb, N, 64, 1, s1, sd1, ws, wd, s2, sd2, wgrid, TB);

    // Layer 2: aggregate(hb, buf2) -> ha, gemm(ha) -> hb
    launch_aggregate(hb, nullptr, ha, N, 64, 0, s2, sd2, nullptr, nullptr, nullptr, nullptr, wgrid, TB);
    {
        dim3 grid(2, mt);
        gemm_fp16_kernel<__half><<<grid, 256>>>(ha, wt + WT2_OFF, b2, hb,
                                                N, 64, 128, 1, 128, nullptr, nullptr, NS);
    }
    // Layer 3
    launch_dots(hb, ws + 64, wd + 64, s1, sd1, N, 128, TB);
    launch_aggregate(hb, nullptr, ha, N, 128, 0, s1, sd1, nullptr, nullptr, nullptr, nullptr, wgrid, TB);
    {
        dim3 grid(3, mt);
        gemm_fp16_kernel<__half><<<grid, 256>>>(ha, wt + WT3_OFF, b3, hb,
                                                N, 128, 192, 1, 192, nullptr, nullptr, NS);
    }
    // Layer 4
    launch_dots(hb, ws + 192, wd + 192, s1, sd1, N, 192, TB);
    launch_aggregate(hb, nullptr, ha, N, 192, 0, s1, sd1, nullptr, nullptr, nullptr, nullptr, wgrid, TB);
    {
        dim3 grid(4, mt);
        gemm_fp16_kernel<__half><<<grid, 256>>>(ha, wt + WT4_OFF, b4, hb,
                                                N, 192, 256, 1, 256, nullptr, nullptr, NS);
    }

    // merged heads: WTZ|WTA contiguous -> one GEMM, Nd=192, split at 128.
    {
        dim3 grid(3, mt);
        gemm_fp16_kernel<float><<<grid, 256>>>(hb, wt + WTZ_OFF, bz, out_z,
                                               N, 256, 192, 0, 128, ba, ap, 128);
    }
    inner_kernel<<<iegrid, TB>>>(out_inner, E);
}

// round 15
// speedup vs baseline: 1.0459x; 1.0459x over previous
#include <cuda_runtime.h>
#include <cuda_fp16.h>
#include <cstdint>
#include <cstddef>

// ---------------------------------------------------------------------------
// GATDecoder round 15: dots fused into GEMM epilogues (atomicAdd partial
// dots, quad-reduced). Standalone dots kernels removed (3 fewer launches,
// 2 fewer full-tensor reads). Score buffers ping-pong with zeroing folded
// into setup / aggregates. Base: R13 pipeline + LDSM GEMM.
// ---------------------------------------------------------------------------

#define MAX_N 50000
#define MAX_E 800000
#define MAX_EDGES_SL (MAX_E + MAX_N)

__device__ __align__(256) __half g_h16a[MAX_N * 256];
__device__ __align__(256) __half g_h16b[MAX_N * 256];
__device__ __align__(256) __half g_aprim16[MAX_N * 64];
__device__ __align__(256) __half g_wt[139264];   // all weights, fp16, [Nd][K]
__device__ float g_ws[384];    // W@a_src: L2 [0,64), L3 [64,192), L4 [192,384)
__device__ float g_wd[384];
__device__ float g_ssrc[MAX_N];   // score buffer A
__device__ float g_sdst[MAX_N];
__device__ float g_ssrc2[MAX_N];  // score buffer B
__device__ float g_sdst2[MAX_N];
__device__ int   g_counts[MAX_N];
__device__ int   g_rowptr[MAX_N + 1];
__device__ int   g_off[MAX_N];
__device__ int   g_colsrc[MAX_EDGES_SL];
__device__ int   g_src[MAX_E];
__device__ int   g_dst[MAX_E];
__device__ int   g_blocksum[64];
__device__ int   g_flag64;

// wt arena offsets (halves). WTZ and WTA contiguous -> merged head GEMM.
#define WT1_OFF 0
#define WT2_OFF 8192
#define WT3_OFF 16384
#define WT4_OFF 40960
#define WTZ_OFF 90112
#define WTA_OFF 122880

// ---------------------------------------------------------------------------
__global__ void detect_dtype_kernel(const int* __restrict__ ei32)
{
    __shared__ int s_any;
    int tid = threadIdx.x;
    if (tid == 0) s_any = 0;
    __syncthreads();
    int any = 0;
    for (int i = tid; i < 1024; i += blockDim.x)
        any |= ei32[2 * i + 1];
    if (any) atomicOr(&s_any, 1);
    __syncthreads();
    if (tid == 0) g_flag64 = (s_any == 0) ? 1 : 0;
}

// fused: z->fp16 + 6 weight transposes + counts init + zero score buffer A
__global__ void setup_kernel(const float* __restrict__ z,
                             const float* __restrict__ W1, const float* __restrict__ W2,
                             const float* __restrict__ W3, const float* __restrict__ W4,
                             const float* __restrict__ Wz, const float* __restrict__ Wa,
                             __half* __restrict__ hb, __half* __restrict__ wt, int N)
{
    int idx = blockIdx.x * blockDim.x + threadIdx.x;
    int A = N * 32;                      // float4 items of z
    if (idx < A) {
        int i = idx * 4;
        float4 v = *reinterpret_cast<const float4*>(z + i);
        __half2 h0 = __floats2half2_rn(v.x, v.y);
        __half2 h1 = __floats2half2_rn(v.z, v.w);
        uint2 packed;
        packed.x = *reinterpret_cast<uint32_t*>(&h0);
        packed.y = *reinterpret_cast<uint32_t*>(&h1);
        *reinterpret_cast<uint2*>(hb + i) = packed;
        return;
    }
    int j = idx - A;
    const float* W; int K, Nd, off, jl;
    if (j < 8192)        { W = W1; K = 128; Nd = 64;  off = WT1_OFF; jl = j; }
    else if (j < 16384)  { W = W2; K = 64;  Nd = 128; off = WT2_OFF; jl = j - 8192; }
    else if (j < 40960)  { W = W3; K = 128; Nd = 192; off = WT3_OFF; jl = j - 16384; }
    else if (j < 90112)  { W = W4; K = 192; Nd = 256; off = WT4_OFF; jl = j - 40960; }
    else if (j < 122880) { W = Wz; K = 256; Nd = 128; off = WTZ_OFF; jl = j - 90112; }
    else if (j < 139264) { W = Wa; K = 256; Nd = 64;  off = WTA_OFF; jl = j - 122880; }
    else {
        int n = j - 139264;
        if (n < N) { g_counts[n] = 1; return; }   // self loop
        n -= N;
        if (n < N) { g_ssrc[n] = 0.f; return; }   // zero buffer A (gemm1 dots)
        n -= N;
        if (n < N) g_sdst[n] = 0.f;
        return;
    }
    int k = jl / Nd, n = jl % Nd;
    wt[off + n * K + k] = __float2half(W[jl]);
}

__global__ void convert_hist_kernel(const void* __restrict__ ei, int E)
{
    int e = blockIdx.x * blockDim.x + threadIdx.x;
    if (e >= E) return;
    int s, d;
    if (g_flag64) {
        const long long* p = (const long long*)ei;
        s = (int)p[e];
        d = (int)p[E + e];
    } else {
        const int* p = (const int*)ei;
        s = p[e];
        d = p[E + e];
    }
    g_src[e] = s;
    g_dst[e] = d;
    atomicAdd(&g_counts[d], 1);
}

// --- parallel 3-phase exclusive scan ---
__global__ void scan1_kernel(int N)
{
    __shared__ int wsum[32];
    int blk = blockIdx.x;
    int tid = threadIdx.x;
    int lane = tid & 31, wid = tid >> 5;
    int i = blk * 1024 + tid;
    int v = (i < N) ? g_counts[i] : 0;
    int x = v;
    #pragma unroll
    for (int o = 1; o < 32; o <<= 1) {
        int t = __shfl_up_sync(0xffffffffu, x, o);
        if (lane >= o) x += t;
    }
    if (lane == 31) wsum[wid] = x;
    __syncthreads();
    if (wid == 0) {
        int y = wsum[lane];
        #pragma unroll
        for (int o = 1; o < 32; o <<= 1) {
            int t = __shfl_up_sync(0xffffffffu, y, o);
            if (lane >= o) y += t;
        }
        wsum[lane] = y;
    }
    __syncthreads();
    int add = (wid > 0) ? wsum[wid - 1] : 0;
    if (i < N) g_rowptr[i] = x + add - v;
    if (tid == 0) g_blocksum[blk] = wsum[31];
}

__global__ void scan2_kernel(int nblk, int N)
{
    __shared__ int s[64];
    int tid = threadIdx.x;
    int v = (tid < nblk) ? g_blocksum[tid] : 0;
    s[tid] = v;
    __syncthreads();
    #pragma unroll
    for (int off = 1; off < 64; off <<= 1) {
        int t = (tid >= off) ? s[tid - off] : 0;
        __syncthreads();
        s[tid] += t;
        __syncthreads();
    }
    g_blocksum[tid] = s[tid] - v;
    if (tid == nblk - 1) g_rowptr[N] = s[tid];
}

__global__ void scan3_fill_kernel(int N)
{
    int i = blockIdx.x * blockDim.x + threadIdx.x;
    if (i >= N) return;
    int p = g_rowptr[i] + g_blocksum[i >> 10];
    g_rowptr[i] = p;
    g_colsrc[p] = i;
    g_off[i] = p + 1;
}

__global__ void scatter_kernel(int E)
{
    int e = blockIdx.x * blockDim.x + threadIdx.x;
    if (e >= E) return;
    int d = g_dst[e];
    int pos = atomicAdd(&g_off[d], 1);
    g_colsrc[pos] = g_src[e];
}

// ---------------------------------------------------------------------------
// cp.async helpers
// ---------------------------------------------------------------------------
__device__ __forceinline__ void cp_async16(void* smem, const void* gmem)
{
    uint32_t saddr = (uint32_t)__cvta_generic_to_shared(smem);
    asm volatile("cp.async.cg.shared.global [%0], [%1], 16;\n"
                 :: "r"(saddr), "l"(gmem));
}
__device__ __forceinline__ void cp_commit()
{
    asm volatile("cp.async.commit_group;\n");
}
template<int NN>
__device__ __forceinline__ void cp_wait()
{
    asm volatile("cp.async.wait_group %0;\n" :: "n"(NN));
}

// ---------------------------------------------------------------------------
// fp16 tensor-core GEMM, 3-stage cp.async, BM=128 BN=64 BK=32, LDSM frags.
// 256 thr = 8 warps (4Mx2N), 32x32 per warp. mma m16n8k16, fp32 accum.
// Split-head mode: bn >= split goes to C2 (fp16, ld = Nd-split) with bias2.
// Fused dots: if dv1 != null, per-row dot of the (post-act) output with
// (dv1, dv2) is atomicAdd-ed into dout1/dout2 (buffers pre-zeroed).
// ---------------------------------------------------------------------------
#define SSTR 40

__device__ __forceinline__ void mma_f16(float c[4], const uint32_t a[4], const uint32_t b[2])
{
    asm volatile(
        "mma.sync.aligned.m16n8k16.row.col.f32.f16.f16.f32 "
        "{%0,%1,%2,%3}, {%4,%5,%6,%7}, {%8,%9}, {%0,%1,%2,%3};"
        : "+f"(c[0]), "+f"(c[1]), "+f"(c[2]), "+f"(c[3])
        : "r"(a[0]), "r"(a[1]), "r"(a[2]), "r"(a[3]), "r"(b[0]), "r"(b[1]));
}

__device__ __forceinline__ void ldsm4(uint32_t r[4], uint32_t addr)
{
    asm volatile(
        "ldmatrix.sync.aligned.m8n8.x4.shared.b16 {%0,%1,%2,%3}, [%4];"
        : "=r"(r[0]), "=r"(r[1]), "=r"(r[2]), "=r"(r[3]) : "r"(addr));
}

__device__ __forceinline__ float lrelu(float x, float s) { return x > 0.f ? x : s * x; }

__device__ __forceinline__ void store2(float* p, float a, float b)
{
    *reinterpret_cast<float2*>(p) = make_float2(a, b);
}
__device__ __forceinline__ void store2(__half* p, float a, float b)
{
    *reinterpret_cast<__half2*>(p) = __floats2half2_rn(a, b);
}

template<typename TC>
__global__ __launch_bounds__(256) void gemm_fp16_kernel(
    const __half* __restrict__ A, const __half* __restrict__ WT,
    const float* __restrict__ bias, TC* __restrict__ C,
    int M, int K, int Nd, int act, int cld,
    const float* __restrict__ bias2, __half* __restrict__ C2, int split,
    const float* __restrict__ dv1, const float* __restrict__ dv2,
    float* __restrict__ dout1, float* __restrict__ dout2)
{
    __shared__ __half As[3][128 * SSTR];
    __shared__ __half Bs[3][64 * SSTR];

    int bm = blockIdx.y * 128;
    int bn = blockIdx.x * 64;
    int tid = threadIdx.x;
    int warp = tid >> 5;
    int lane = tid & 31;
    int g = lane >> 2;
    int t = lane & 3;
    int warpM = warp >> 1;
    int warpN = warp & 1;

    int arow0 = tid >> 2;
    int arow1 = arow0 + 64;
    int aq = (tid & 3) << 3;
    int ag0 = (bm + arow0 < M) ? (bm + arow0) : (M - 1);
    int ag1 = (bm + arow1 < M) ? (bm + arow1) : (M - 1);
    int brow = tid >> 2;
    int bq = aq;

    const __half* Bg = WT + (size_t)(bn + brow) * K + bq;
    const __half* Ag0 = A + (size_t)ag0 * K + aq;
    const __half* Ag1 = A + (size_t)ag1 * K + aq;

    uint32_t offA = (uint32_t)(((warpM * 32 + (lane & 15)) * SSTR + ((lane >> 4) << 3)) << 1);
    uint32_t offB = (uint32_t)(((warpN * 32 + lane) * SSTR) << 1);

    uint32_t asb[3], bsb[3];
    #pragma unroll
    for (int i = 0; i < 3; i++) {
        asb[i] = (uint32_t)__cvta_generic_to_shared(As[i]);
        bsb[i] = (uint32_t)__cvta_generic_to_shared(Bs[i]);
    }

    float acc[2][4][4];
    #pragma unroll
    for (int mf = 0; mf < 2; mf++)
        #pragma unroll
        for (int nf = 0; nf < 4; nf++)
            #pragma unroll
            for (int i = 0; i < 4; i++) acc[mf][nf][i] = 0.f;

    int iters = K >> 5;

    cp_async16(As[0] + arow0 * SSTR + aq, Ag0);
    cp_async16(As[0] + arow1 * SSTR + aq, Ag1);
    cp_async16(Bs[0] + brow * SSTR + bq, Bg);
    cp_commit();
    if (iters > 1) {
        cp_async16(As[1] + arow0 * SSTR + aq, Ag0 + 32);
        cp_async16(As[1] + arow1 * SSTR + aq, Ag1 + 32);
        cp_async16(Bs[1] + brow * SSTR + bq, Bg + 32);
    }
    cp_commit();

    int buf = 0;
    for (int it = 0; it < iters; it++) {
        int pre = it + 2;
        if (pre < iters) {
            int nb = pre - (pre / 3) * 3;
            int off = pre << 5;
            cp_async16(As[nb] + arow0 * SSTR + aq, Ag0 + off);
            cp_async16(As[nb] + arow1 * SSTR + aq, Ag1 + off);
            cp_async16(Bs[nb] + brow * SSTR + bq, Bg + off);
        }
        cp_commit();
        cp_wait<2>();
        __syncthreads();

        uint32_t ab = asb[buf];
        uint32_t bb = bsb[buf];
        #pragma unroll
        for (int kk = 0; kk < 32; kk += 16) {
            uint32_t a0[4], a1[4], b0[4], b1[4];
            ldsm4(a0, ab + offA + (kk << 1));
            ldsm4(a1, ab + offA + ((16 * SSTR + kk) << 1));
            ldsm4(b0, bb + offB + (kk << 1));
            ldsm4(b1, bb + offB + ((kk + 8) << 1));
            #pragma unroll
            for (int nf = 0; nf < 4; nf++) {
                uint32_t bfrag[2] = {b0[nf], b1[nf]};
                mma_f16(acc[0][nf], a0, bfrag);
                mma_f16(acc[1][nf], a1, bfrag);
            }
        }
        __syncthreads();
        buf++;
        if (buf == 3) buf = 0;
    }

    if (bn < split) {
        #pragma unroll
        for (int mf = 0; mf < 2; mf++) {
            int r0 = bm + warpM * 32 + mf * 16 + g;
            float d1a = 0.f, d2a = 0.f, d1b = 0.f, d2b = 0.f;
            #pragma unroll
            for (int nf = 0; nf < 4; nf++) {
                int col = bn + warpN * 32 + nf * 8 + t * 2;
                float bx = 0.f, by = 0.f;
                if (bias) { bx = bias[col]; by = bias[col + 1]; }
                float v0 = acc[mf][nf][0] + bx, v1 = acc[mf][nf][1] + by;
                float v2 = acc[mf][nf][2] + bx, v3 = acc[mf][nf][3] + by;
                if (act) {
                    v0 = lrelu(v0, 0.01f); v1 = lrelu(v1, 0.01f);
                    v2 = lrelu(v2, 0.01f); v3 = lrelu(v3, 0.01f);
                }
                if (r0 < M)
                    store2(C + (size_t)r0 * cld + col, v0, v1);
                if (r0 + 8 < M)
                    store2(C + (size_t)(r0 + 8) * cld + col, v2, v3);
                if (dv1) {
                    float w1 = dv1[col], w1b = dv1[col + 1];
                    float w2 = dv2[col], w2b = dv2[col + 1];
                    d1a += v0 * w1 + v1 * w1b;
                    d2a += v0 * w2 + v1 * w2b;
                    d1b += v2 * w1 + v3 * w1b;
                    d2b += v2 * w2 + v3 * w2b;
                }
            }
            if (dv1) {
                #pragma unroll
                for (int o = 1; o <= 2; o <<= 1) {
                    d1a += __shfl_xor_sync(0xffffffffu, d1a, o);
                    d2a += __shfl_xor_sync(0xffffffffu, d2a, o);
                    d1b += __shfl_xor_sync(0xffffffffu, d1b, o);
                    d2b += __shfl_xor_sync(0xffffffffu, d2b, o);
                }
                if (t == 0) {
                    if (r0 < M) {
                        atomicAdd(dout1 + r0, d1a);
                        atomicAdd(dout2 + r0, d2a);
                    }
                    if (r0 + 8 < M) {
                        atomicAdd(dout1 + r0 + 8, d1b);
                        atomicAdd(dout2 + r0 + 8, d2b);
                    }
                }
            }
        }
    } else {
        int ld2 = Nd - split;
        #pragma unroll
        for (int mf = 0; mf < 2; mf++) {
            int r0 = bm + warpM * 32 + mf * 16 + g;
            #pragma unroll
            for (int nf = 0; nf < 4; nf++) {
                int col = bn + warpN * 32 + nf * 8 + t * 2 - split;
                float bx = bias2[col], by = bias2[col + 1];
                float v0 = acc[mf][nf][0] + bx, v1 = acc[mf][nf][1] + by;
                float v2 = acc[mf][nf][2] + bx, v3 = acc[mf][nf][3] + by;
                if (r0 < M)
                    store2(C2 + (size_t)r0 * ld2 + col, v0, v1);
                if (r0 + 8 < M)
                    store2(C2 + (size_t)(r0 + 8) * ld2 + col, v2, v3);
            }
        }
    }
}

// ---------------------------------------------------------------------------
// wvec for layers 2-4 in one launch: g_ws/g_wd[base+k] = W[k,:] . a
// ---------------------------------------------------------------------------
__global__ void wvec_all_kernel(const float* __restrict__ W2, const float* __restrict__ W3,
                                const float* __restrict__ W4,
                                const float* __restrict__ as2, const float* __restrict__ ad2,
                                const float* __restrict__ as3, const float* __restrict__ ad3,
                                const float* __restrict__ as4, const float* __restrict__ ad4)
{
    int w = (blockIdx.x * blockDim.x + threadIdx.x) >> 5;
    int lane = threadIdx.x & 31;
    if (w >= 384) return;
    const float* W; const float* as; const float* ad; int Do, base, k;
    if (w < 64)       { W = W2; as = as2; ad = ad2; Do = 128; base = 0;   k = w; }
    else if (w < 192) { W = W3; as = as3; ad = ad3; Do = 192; base = 64;  k = w - 64; }
    else              { W = W4; as = as4; ad = ad4; Do = 256; base = 192; k = w - 192; }
    const float* wr = W + (size_t)k * Do;
    float s1 = 0.f, s2 = 0.f;
    for (int d = lane; d < Do; d += 32) {
        float v = wr[d];
        s1 += v * as[d];
        s2 += v * ad[d];
    }
    #pragma unroll
    for (int o = 16; o > 0; o >>= 1) {
        s1 += __shfl_xor_sync(0xffffffffu, s1, o);
        s2 += __shfl_xor_sync(0xffffffffu, s2, o);
    }
    if (lane == 0) {
        g_ws[base + k] = s1;
        g_wd[base + k] = s2;
    }
}

// ---------------------------------------------------------------------------
__device__ __forceinline__ void unpack8(int4 raw, float f[8])
{
    const __half2* hp = reinterpret_cast<const __half2*>(&raw);
    #pragma unroll
    for (int r = 0; r < 4; r++) {
        float2 v = __half22float2(hp[r]);
        f[2 * r] = v.x;
        f[2 * r + 1] = v.y;
    }
}

// ---------------------------------------------------------------------------
// Aggregate: warp per node, 4 edge-groups of 8 lanes, online softmax per
// group, shuffle merge, prefetch pipeline. Optional fused dot of OUTPUT row
// -> (dout1, dout2). Optional zeroing of a recycled score buffer (zb1, zb2).
// ---------------------------------------------------------------------------
template<int D>
__global__ void aggregate_kernel(const __half* __restrict__ feat,
                                 const float* __restrict__ bias,
                                 __half* __restrict__ out,
                                 int N, int act,
                                 const float* __restrict__ ssrc,
                                 const float* __restrict__ sdst,
                                 const float* __restrict__ dv1,
                                 const float* __restrict__ dv2,
                                 float* __restrict__ dout1,
                                 float* __restrict__ dout2,
                                 float* __restrict__ zb1,
                                 float* __restrict__ zb2)
{
    constexpr int V = D / 8;
    constexpr int NI4 = V / 8;
    int warp = (blockIdx.x * blockDim.x + threadIdx.x) >> 5;
    int lane = threadIdx.x & 31;
    int grp = lane >> 3, gl = lane & 7;
    if (warp >= N) return;

    // zero the recycled score buffer (disjoint from ssrc/sdst being read)
    if (zb1 && lane == 0) {
        zb1[warp] = 0.f;
        zb2[warp] = 0.f;
    }

    int beg = g_rowptr[warp];
    int end = g_rowptr[warp + 1];
    float sd = sdst[warp];

    float m = -1e30f;
    float s = 0.f;
    float acc[V];
    #pragma unroll
    for (int v = 0; v < V; v++) acc[v] = 0.f;

    int j = beg + grp;
    int src = 0;
    float sv = 0.f;
    if (j < end) {
        src = g_colsrc[j];
        sv = ssrc[src];
    }
    while (j < end) {
        int jn = j + 4;
        int srcn = 0;
        float svn = 0.f;
        if (jn < end) {
            srcn = g_colsrc[jn];
            svn = ssrc[srcn];
        }
        float a = lrelu(sv + sd, 0.2f);
        if (a > m) {
            float f = __expf(m - a);
            s *= f;
            #pragma unroll
            for (int v = 0; v < V; v++) acc[v] *= f;
            m = a;
        }
        float w = __expf(a - m);
        s += w;
        const int4* fr = reinterpret_cast<const int4*>(feat + (size_t)src * D + gl * V);
        #pragma unroll
        for (int q = 0; q < NI4; q++) {
            float f[8];
            unpack8(fr[q], f);
            #pragma unroll
            for (int r = 0; r < 8; r++)
                acc[q * 8 + r] += w * f[r];
        }
        j = jn;
        src = srcn;
        sv = svn;
    }

    #pragma unroll
    for (int off = 8; off <= 16; off <<= 1) {
        float m2 = __shfl_xor_sync(0xffffffffu, m, off);
        float s2 = __shfl_xor_sync(0xffffffffu, s, off);
        float mn = fmaxf(m, m2);
        float f1 = __expf(m - mn);
        float f2 = __expf(m2 - mn);
        s = s * f1 + s2 * f2;
        #pragma unroll
        for (int v = 0; v < V; v++) {
            float o = __shfl_xor_sync(0xffffffffu, acc[v], off);
            acc[v] = acc[v] * f1 + o * f2;
        }
        m = mn;
    }

    float inv = 1.f / (s + 1e-16f);
    float d1 = 0.f, d2 = 0.f;
    if (grp == 0) {
        __half* orow = out + (size_t)warp * D + gl * V;
        #pragma unroll
        for (int q = 0; q < NI4; q++) {
            int4 raw;
            __half2* hp = reinterpret_cast<__half2*>(&raw);
            #pragma unroll
            for (int r = 0; r < 4; r++) {
                int d = gl * V + q * 8 + 2 * r;
                float v0 = acc[q * 8 + 2 * r] * inv;
                float v1 = acc[q * 8 + 2 * r + 1] * inv;
                if (bias) { v0 += bias[d]; v1 += bias[d + 1]; }
                if (act) { v0 = lrelu(v0, 0.01f); v1 = lrelu(v1, 0.01f); }
                hp[r] = __floats2half2_rn(v0, v1);
                if (dv1) {
                    d1 += v0 * dv1[d] + v1 * dv1[d + 1];
                    d2 += v0 * dv2[d] + v1 * dv2[d + 1];
                }
            }
            *reinterpret_cast<int4*>(orow + q * 8) = raw;
        }
    }
    if (dv1) {
        #pragma unroll
        for (int o = 4; o > 0; o >>= 1) {
            d1 += __shfl_xor_sync(0xffffffffu, d1, o);
            d2 += __shfl_xor_sync(0xffffffffu, d2, o);
        }
        if (grp == 0 && gl == 0) {
            dout1[warp] = d1;
            dout2[warp] = d2;
        }
    }
}

// ---------------------------------------------------------------------------
// inner: 8-lane groups, 4 edges per warp, int4 loads (D=64).
// ---------------------------------------------------------------------------
__global__ void inner_kernel(float* __restrict__ out, int E)
{
    int warp = (blockIdx.x * blockDim.x + threadIdx.x) >> 5;
    int lane = threadIdx.x & 31;
    int grp = lane >> 3, gl = lane & 7;
    int e = warp * 4 + grp;
    bool valid = e < E;

    float acc = 0.f;
    if (valid) {
        int s = g_src[e];
        int d = g_dst[e];
        int4 a4 = *reinterpret_cast<const int4*>(g_aprim16 + (size_t)s * 64 + gl * 8);
        int4 b4 = *reinterpret_cast<const int4*>(g_aprim16 + (size_t)d * 64 + gl * 8);
        float fa[8], fb[8];
        unpack8(a4, fa);
        unpack8(b4, fb);
        #pragma unroll
        for (int r = 0; r < 8; r++)
            acc += fa[r] * fb[r];
    }
    #pragma unroll
    for (int o = 4; o > 0; o >>= 1)
        acc += __shfl_xor_sync(0xffffffffu, acc, o);
    if (valid && gl == 0)
        out[e] = 1.f / (1.f + expf(-acc));
}

// ---------------------------------------------------------------------------
static void launch_aggregate(const __half* feat, const float* bias, __half* out,
                             int N, int D, int act,
                             const float* ssrc, const float* sdst,
                             const float* dv1, const float* dv2,
                             float* dout1, float* dout2,
                             float* zb1, float* zb2,
                             int wgrid, int TB)
{
    switch (D) {
        case 64:  aggregate_kernel<64> <<<wgrid, TB>>>(feat, bias, out, N, act, ssrc, sdst, dv1, dv2, dout1, dout2, zb1, zb2); break;
        case 128: aggregate_kernel<128><<<wgrid, TB>>>(feat, bias, out, N, act, ssrc, sdst, dv1, dv2, dout1, dout2, zb1, zb2); break;
        case 192: aggregate_kernel<192><<<wgrid, TB>>>(feat, bias, out, N, act, ssrc, sdst, dv1, dv2, dout1, dout2, zb1, zb2); break;
        default:  break;
    }
}

extern "C" void kernel_launch(void* const* d_in, const int* in_sizes, int n_in,
                              void* d_out, int out_size)
{
    const float* z   = (const float*)d_in[0];
    const void*  ei  = d_in[1];
    const float* W1  = (const float*)d_in[2];
    const float* as1 = (const float*)d_in[3];
    const float* ad1 = (const float*)d_in[4];
    const float* b1  = (const float*)d_in[5];
    const float* W2  = (const float*)d_in[6];
    const float* as2 = (const float*)d_in[7];
    const float* ad2 = (const float*)d_in[8];
    const float* b2  = (const float*)d_in[9];
    const float* W3  = (const float*)d_in[10];
    const float* as3 = (const float*)d_in[11];
    const float* ad3 = (const float*)d_in[12];
    const float* b3  = (const float*)d_in[13];
    const float* W4  = (const float*)d_in[14];
    const float* as4 = (const float*)d_in[15];
    const float* ad4 = (const float*)d_in[16];
    const float* b4  = (const float*)d_in[17];
    const float* Wz  = (const float*)d_in[18];
    const float* bz  = (const float*)d_in[19];
    const float* Wa  = (const float*)d_in[20];
    const float* ba  = (const float*)d_in[21];

    int N = in_sizes[0] / 128;
    if (N > MAX_N) N = MAX_N;
    int E = in_sizes[1] / 2;
    if (E > MAX_E) E = MAX_E;

    float* out_z     = (float*)d_out;
    float* out_inner = (float*)d_out + (size_t)N * 128;

    __half* ha;  cudaGetSymbolAddress((void**)&ha, g_h16a);
    __half* hb;  cudaGetSymbolAddress((void**)&hb, g_h16b);
    __half* ap;  cudaGetSymbolAddress((void**)&ap, g_aprim16);
    __half* wt;  cudaGetSymbolAddress((void**)&wt, g_wt);
    float* ws;   cudaGetSymbolAddress((void**)&ws, g_ws);
    float* wd;   cudaGetSymbolAddress((void**)&wd, g_wd);
    float* s1;   cudaGetSymbolAddress((void**)&s1, g_ssrc);
    float* sd1;  cudaGetSymbolAddress((void**)&sd1, g_sdst);
    float* s2;   cudaGetSymbolAddress((void**)&s2, g_ssrc2);
    float* sd2;  cudaGetSymbolAddress((void**)&sd2, g_sdst2);

    const int TB = 256;
    int egrid = (E + TB - 1) / TB;
    int ngrid = (N + TB - 1) / TB;
    int wgrid = (N * 32 + TB - 1) / TB;               // warp-per-node
    int iegrid = (((E + 3) / 4) * 32 + TB - 1) / TB;  // 4 edges per warp
    int nblk = (N + 1023) / 1024;
    int setup_items = N * 32 + 139264 + 3 * N;
    int sgrid = (setup_items + TB - 1) / TB;
    int mt = (N + 127) / 128;
    const int NS = 1 << 30;                           // "no split"

    // 1: dtype detect; 2: fused setup (also zeroes score buffer A)
    detect_dtype_kernel<<<1, 256>>>((const int*)ei);
    setup_kernel<<<sgrid, TB>>>(z, W1, W2, W3, W4, Wz, Wa, hb, wt, N);
    // 3: edge convert + histogram
    convert_hist_kernel<<<egrid, TB>>>(ei, E);
    // 4: L1 GEMM with fused L1 dots -> buffer A (atomic; pre-zeroed)
    {
        dim3 grid(1, mt);
        gemm_fp16_kernel<__half><<<grid, 256>>>(hb, wt + WT1_OFF, nullptr, ha,
                                                N, 128, 64, 0, 64, nullptr, nullptr, NS,
                                                as1, ad1, s1, sd1);
    }
    // 5: wvec for layers 2-4; 6-9: CSR build
    wvec_all_kernel<<<48, TB>>>(W2, W3, W4, as2, ad2, as3, ad3, as4, ad4);
    scan1_kernel<<<nblk, 1024>>>(N);
    scan2_kernel<<<1, 64>>>(nblk, N);
    scan3_fill_kernel<<<ngrid, TB>>>(N);
    scatter_kernel<<<egrid, TB>>>(E);

    // Layer 1 aggregate: ha -> hb; reads buf A, fused L2 dots -> buf B
    launch_aggregate(ha, b1, hb, N, 64, 1, s1, sd1, ws, wd, s2, sd2,
                     nullptr, nullptr, wgrid, TB);

    // Layer 2: aggregate(hb, buf B) -> ha (zeroes buf A); gemm -> hb with
    // fused L3 dots -> buf A
    launch_aggregate(hb, nullptr, ha, N, 64, 0, s2, sd2, nullptr, nullptr,
                     nullptr, nullptr, s1, sd1, wgrid, TB);
    {
        dim3 grid(2, mt);
        gemm_fp16_kernel<__half><<<grid, 256>>>(ha, wt + WT2_OFF, b2, hb,
                                                N, 64, 128, 1, 128, nullptr, nullptr, NS,
                                                ws + 64, wd + 64, s1, sd1);
    }
    // Layer 3: aggregate(hb, buf A) -> ha (zeroes buf B); gemm -> hb with
    // fused L4 dots -> buf B
    launch_aggregate(hb, nullptr, ha, N, 128, 0, s1, sd1, nullptr, nullptr,
                     nullptr, nullptr, s2, sd2, wgrid, TB);
    {
        dim3 grid(3, mt);
        gemm_fp16_kernel<__half><<<grid, 256>>>(ha, wt + WT3_OFF, b3, hb,
                                                N, 128, 192, 1, 192, nullptr, nullptr, NS,
                                                ws + 192, wd + 192, s2, sd2);
    }
    // Layer 4: aggregate(hb, buf B) -> ha; gemm -> hb (no fused dots)
    launch_aggregate(hb, nullptr, ha, N, 192, 0, s2, sd2, nullptr, nullptr,
                     nullptr, nullptr, nullptr, nullptr, wgrid, TB);
    {
        dim3 grid(4, mt);
        gemm_fp16_kernel<__half><<<grid, 256>>>(ha, wt + WT4_OFF, b4, hb,
                                                N, 192, 256, 1, 256, nullptr, nullptr, NS,
                                                nullptr, nullptr, nullptr, nullptr);
    }

    // merged heads: WTZ|WTA contiguous -> one GEMM, Nd=192, split at 128.
    {
        dim3 grid(3, mt);
        gemm_fp16_kernel<float><<<grid, 256>>>(hb, wt + WTZ_OFF, bz, out_z,
                                               N, 256, 192, 0, 128, ba, ap, 128,
                                               nullptr, nullptr, nullptr, nullptr);
    }
    inner_kernel<<<iegrid, TB>>>(out_inner, E);
}

// round 17
// speedup vs baseline: 1.0753x; 1.0281x over previous
#include <cuda_runtime.h>
#include <cuda_fp16.h>
#include <cstdint>
#include <cstddef>

// ---------------------------------------------------------------------------
// GATDecoder round 17: R16 with the lookback-scan race FIXED (packed 64-bit
// status|value published atomically). Single-pass scan, setup-fused wvec,
// 2-edge-unrolled aggregate, fused-dots GEMM epilogues, merged heads.
// ---------------------------------------------------------------------------

#define MAX_N 50000
#define MAX_E 800000
#define MAX_EDGES_SL (MAX_E + MAX_N)

__device__ __align__(256) __half g_h16a[MAX_N * 256];
__device__ __align__(256) __half g_h16b[MAX_N * 256];
__device__ __align__(256) __half g_aprim16[MAX_N * 64];
__device__ __align__(256) __half g_wt[139264];   // all weights, fp16, [Nd][K]
__device__ float g_ws[384];    // W@a_src: L2 [0,64), L3 [64,192), L4 [192,384)
__device__ float g_wd[384];
__device__ float g_ssrc[MAX_N];   // score buffer A
__device__ float g_sdst[MAX_N];
__device__ float g_ssrc2[MAX_N];  // score buffer B
__device__ float g_sdst2[MAX_N];
__device__ int   g_counts[MAX_N];
__device__ int   g_rowptr[MAX_N + 1];
__device__ int   g_off[MAX_N];
__device__ int   g_colsrc[MAX_EDGES_SL];
__device__ int   g_src[MAX_E];
__device__ int   g_dst[MAX_E];
__device__ __align__(8) unsigned long long g_scan_pack[64]; // (flag<<32)|value
__device__ int   g_flag64;

#define WT1_OFF 0
#define WT2_OFF 8192
#define WT3_OFF 16384
#define WT4_OFF 40960
#define WTZ_OFF 90112
#define WTA_OFF 122880

// ---------------------------------------------------------------------------
__global__ void detect_dtype_kernel(const int* __restrict__ ei32)
{
    __shared__ int s_any;
    int tid = threadIdx.x;
    if (tid == 0) s_any = 0;
    __syncthreads();
    int any = 0;
    for (int i = tid; i < 1024; i += blockDim.x)
        any |= ei32[2 * i + 1];
    if (any) atomicOr(&s_any, 1);
    __syncthreads();
    if (tid == 0) g_flag64 = (s_any == 0) ? 1 : 0;
}

// fused: z->fp16 + 6 weight transposes + wvec(L2..L4) + counts init +
// zero score buffer A + zero scan state
__global__ void setup_kernel(const float* __restrict__ z,
                             const float* __restrict__ W1, const float* __restrict__ W2,
                             const float* __restrict__ W3, const float* __restrict__ W4,
                             const float* __restrict__ Wz, const float* __restrict__ Wa,
                             const float* __restrict__ as2, const float* __restrict__ ad2,
                             const float* __restrict__ as3, const float* __restrict__ ad3,
                             const float* __restrict__ as4, const float* __restrict__ ad4,
                             __half* __restrict__ hb, __half* __restrict__ wt, int N)
{
    int idx = blockIdx.x * blockDim.x + threadIdx.x;
    int A = N * 32;                       // z float4 items
    if (idx < A) {
        int i = idx * 4;
        float4 v = *reinterpret_cast<const float4*>(z + i);
        __half2 h0 = __floats2half2_rn(v.x, v.y);
        __half2 h1 = __floats2half2_rn(v.z, v.w);
        uint2 packed;
        packed.x = *reinterpret_cast<uint32_t*>(&h0);
        packed.y = *reinterpret_cast<uint32_t*>(&h1);
        *reinterpret_cast<uint2*>(hb + i) = packed;
        return;
    }
    int j = idx - A;
    if (j < 139264) {                     // weight transposes
        const float* W; int K, Nd, off, jl;
        if (j < 8192)        { W = W1; K = 128; Nd = 64;  off = WT1_OFF; jl = j; }
        else if (j < 16384)  { W = W2; K = 64;  Nd = 128; off = WT2_OFF; jl = j - 8192; }
        else if (j < 40960)  { W = W3; K = 128; Nd = 192; off = WT3_OFF; jl = j - 16384; }
        else if (j < 90112)  { W = W4; K = 192; Nd = 256; off = WT4_OFF; jl = j - 40960; }
        else if (j < 122880) { W = Wz; K = 256; Nd = 128; off = WTZ_OFF; jl = j - 90112; }
        else                 { W = Wa; K = 256; Nd = 64;  off = WTA_OFF; jl = j - 122880; }
        int k = jl / Nd, n = jl % Nd;
        wt[off + n * K + k] = __float2half(W[jl]);
        return;
    }
    j -= 139264;
    if (j < 384 * 32) {                   // wvec: warp-aligned segment
        int w = j >> 5;
        int lane = j & 31;
        const float* W; const float* as; const float* ad; int Do, base, k;
        if (w < 64)       { W = W2; as = as2; ad = ad2; Do = 128; base = 0;   k = w; }
        else if (w < 192) { W = W3; as = as3; ad = ad3; Do = 192; base = 64;  k = w - 64; }
        else              { W = W4; as = as4; ad = ad4; Do = 256; base = 192; k = w - 192; }
        const float* wr = W + (size_t)k * Do;
        float s1 = 0.f, s2 = 0.f;
        for (int d = lane; d < Do; d += 32) {
            float v = wr[d];
            s1 += v * as[d];
            s2 += v * ad[d];
        }
        #pragma unroll
        for (int o = 16; o > 0; o >>= 1) {
            s1 += __shfl_xor_sync(0xffffffffu, s1, o);
            s2 += __shfl_xor_sync(0xffffffffu, s2, o);
        }
        if (lane == 0) {
            g_ws[base + k] = s1;
            g_wd[base + k] = s2;
        }
        return;
    }
    j -= 384 * 32;
    if (j < N) { g_counts[j] = 1; return; }        // self loop
    j -= N;
    if (j < N) { g_ssrc[j] = 0.f; return; }        // zero buffer A
    j -= N;
    if (j < N) { g_sdst[j] = 0.f; return; }
    j -= N;
    if (j < 64) g_scan_pack[j] = 0ull;
    return;
}

__global__ void convert_hist_kernel(const void* __restrict__ ei, int E)
{
    int e = blockIdx.x * blockDim.x + threadIdx.x;
    if (e >= E) return;
    int s, d;
    if (g_flag64) {
        const long long* p = (const long long*)ei;
        s = (int)p[e];
        d = (int)p[E + e];
    } else {
        const int* p = (const int*)ei;
        s = p[e];
        d = p[E + e];
    }
    g_src[e] = s;
    g_dst[e] = d;
    atomicAdd(&g_counts[d], 1);
}

// ---------------------------------------------------------------------------
// Single-pass decoupled-lookback scan + fill. Race-free: (flag, value) are
// published as ONE aligned 64-bit word via atomicExch; each state written
// exactly once. All <=49 blocks are co-resident -> lookback cannot deadlock.
// ---------------------------------------------------------------------------
__global__ void scan_fused_kernel(int N, int nblk)
{
    __shared__ int wsum[32];
    __shared__ int s_prefix;
    int blk = blockIdx.x;
    int tid = threadIdx.x;
    int lane = tid & 31, wid = tid >> 5;
    int i = blk * 1024 + tid;
    int v = (i < N) ? g_counts[i] : 0;
    int x = v;
    #pragma unroll
    for (int o = 1; o < 32; o <<= 1) {
        int t = __shfl_up_sync(0xffffffffu, x, o);
        if (lane >= o) x += t;
    }
    if (lane == 31) wsum[wid] = x;
    __syncthreads();
    if (wid == 0) {
        int y = wsum[lane];
        #pragma unroll
        for (int o = 1; o < 32; o <<= 1) {
            int t = __shfl_up_sync(0xffffffffu, y, o);
            if (lane >= o) y += t;
        }
        wsum[lane] = y;
    }
    __syncthreads();
    int add = (wid > 0) ? wsum[wid - 1] : 0;
    int local_excl = x + add - v;
    int total = wsum[31];

    if (tid == 0) {
        if (blk == 0) {
            atomicExch(&g_scan_pack[0],
                       (2ull << 32) | (unsigned long long)(unsigned)total);
            s_prefix = 0;
            if (nblk == 1) g_rowptr[N] = total;
        } else {
            atomicExch(&g_scan_pack[blk],
                       (1ull << 32) | (unsigned long long)(unsigned)total);
            int pref = 0;
            int p = blk - 1;
            while (true) {
                unsigned long long pk;
                do {
                    pk = atomicAdd(&g_scan_pack[p], 0ull);   // atomic 64-bit read
                } while ((pk >> 32) == 0ull);
                int val = (int)(unsigned)(pk & 0xffffffffull);
                pref += val;
                if ((pk >> 32) == 2ull) break;
                p--;
            }
            atomicExch(&g_scan_pack[blk],
                       (2ull << 32) | (unsigned long long)(unsigned)(pref + total));
            s_prefix = pref;
            if (blk == nblk - 1) g_rowptr[N] = pref + total;
        }
    }
    __syncthreads();
    int pfx = s_prefix;
    if (i < N) {
        int pos = local_excl + pfx;
        g_rowptr[i] = pos;
        g_colsrc[pos] = i;               // self loop first
        g_off[i] = pos + 1;
    }
}

__global__ void scatter_kernel(int E)
{
    int e = blockIdx.x * blockDim.x + threadIdx.x;
    if (e >= E) return;
    int d = g_dst[e];
    int pos = atomicAdd(&g_off[d], 1);
    g_colsrc[pos] = g_src[e];
}

// ---------------------------------------------------------------------------
// cp.async helpers
// ---------------------------------------------------------------------------
__device__ __forceinline__ void cp_async16(void* smem, const void* gmem)
{
    uint32_t saddr = (uint32_t)__cvta_generic_to_shared(smem);
    asm volatile("cp.async.cg.shared.global [%0], [%1], 16;\n"
                 :: "r"(saddr), "l"(gmem));
}
__device__ __forceinline__ void cp_commit()
{
    asm volatile("cp.async.commit_group;\n");
}
template<int NN>
__device__ __forceinline__ void cp_wait()
{
    asm volatile("cp.async.wait_group %0;\n" :: "n"(NN));
}

// ---------------------------------------------------------------------------
// fp16 tensor-core GEMM, 3-stage cp.async, BM=128 BN=64 BK=32, LDSM frags.
// Split-head mode + fused-dots epilogue.
// ---------------------------------------------------------------------------
#define SSTR 40

__device__ __forceinline__ void mma_f16(float c[4], const uint32_t a[4], const uint32_t b[2])
{
    asm volatile(
        "mma.sync.aligned.m16n8k16.row.col.f32.f16.f16.f32 "
        "{%0,%1,%2,%3}, {%4,%5,%6,%7}, {%8,%9}, {%0,%1,%2,%3};"
        : "+f"(c[0]), "+f"(c[1]), "+f"(c[2]), "+f"(c[3])
        : "r"(a[0]), "r"(a[1]), "r"(a[2]), "r"(a[3]), "r"(b[0]), "r"(b[1]));
}

__device__ __forceinline__ void ldsm4(uint32_t r[4], uint32_t addr)
{
    asm volatile(
        "ldmatrix.sync.aligned.m8n8.x4.shared.b16 {%0,%1,%2,%3}, [%4];"
        : "=r"(r[0]), "=r"(r[1]), "=r"(r[2]), "=r"(r[3]) : "r"(addr));
}

__device__ __forceinline__ float lrelu(float x, float s) { return x > 0.f ? x : s * x; }

__device__ __forceinline__ void store2(float* p, float a, float b)
{
    *reinterpret_cast<float2*>(p) = make_float2(a, b);
}
__device__ __forceinline__ void store2(__half* p, float a, float b)
{
    *reinterpret_cast<__half2*>(p) = __floats2half2_rn(a, b);
}

template<typename TC>
__global__ __launch_bounds__(256) void gemm_fp16_kernel(
    const __half* __restrict__ A, const __half* __restrict__ WT,
    const float* __restrict__ bias, TC* __restrict__ C,
    int M, int K, int Nd, int act, int cld,
    const float* __restrict__ bias2, __half* __restrict__ C2, int split,
    const float* __restrict__ dv1, const float* __restrict__ dv2,
    float* __restrict__ dout1, float* __restrict__ dout2)
{
    __shared__ __half As[3][128 * SSTR];
    __shared__ __half Bs[3][64 * SSTR];

    int bm = blockIdx.y * 128;
    int bn = blockIdx.x * 64;
    int tid = threadIdx.x;
    int warp = tid >> 5;
    int lane = tid & 31;
    int g = lane >> 2;
    int t = lane & 3;
    int warpM = warp >> 1;
    int warpN = warp & 1;

    int arow0 = tid >> 2;
    int arow1 = arow0 + 64;
    int aq = (tid & 3) << 3;
    int ag0 = (bm + arow0 < M) ? (bm + arow0) : (M - 1);
    int ag1 = (bm + arow1 < M) ? (bm + arow1) : (M - 1);
    int brow = tid >> 2;
    int bq = aq;

    const __half* Bg = WT + (size_t)(bn + brow) * K + bq;
    const __half* Ag0 = A + (size_t)ag0 * K + aq;
    const __half* Ag1 = A + (size_t)ag1 * K + aq;

    uint32_t offA = (uint32_t)(((warpM * 32 + (lane & 15)) * SSTR + ((lane >> 4) << 3)) << 1);
    uint32_t offB = (uint32_t)(((warpN * 32 + lane) * SSTR) << 1);

    uint32_t asb[3], bsb[3];
    #pragma unroll
    for (int i = 0; i < 3; i++) {
        asb[i] = (uint32_t)__cvta_generic_to_shared(As[i]);
        bsb[i] = (uint32_t)__cvta_generic_to_shared(Bs[i]);
    }

    float acc[2][4][4];
    #pragma unroll
    for (int mf = 0; mf < 2; mf++)
        #pragma unroll
        for (int nf = 0; nf < 4; nf++)
            #pragma unroll
            for (int i = 0; i < 4; i++) acc[mf][nf][i] = 0.f;

    int iters = K >> 5;

    cp_async16(As[0] + arow0 * SSTR + aq, Ag0);
    cp_async16(As[0] + arow1 * SSTR + aq, Ag1);
    cp_async16(Bs[0] + brow * SSTR + bq, Bg);
    cp_commit();
    if (iters > 1) {
        cp_async16(As[1] + arow0 * SSTR + aq, Ag0 + 32);
        cp_async16(As[1] + arow1 * SSTR + aq, Ag1 + 32);
        cp_async16(Bs[1] + brow * SSTR + bq, Bg + 32);
    }
    cp_commit();

    int buf = 0;
    for (int it = 0; it < iters; it++) {
        int pre = it + 2;
        if (pre < iters) {
            int nb = pre - (pre / 3) * 3;
            int off = pre << 5;
            cp_async16(As[nb] + arow0 * SSTR + aq, Ag0 + off);
            cp_async16(As[nb] + arow1 * SSTR + aq, Ag1 + off);
            cp_async16(Bs[nb] + brow * SSTR + bq, Bg + off);
        }
        cp_commit();
        cp_wait<2>();
        __syncthreads();

        uint32_t ab = asb[buf];
        uint32_t bb = bsb[buf];
        #pragma unroll
        for (int kk = 0; kk < 32; kk += 16) {
            uint32_t a0[4], a1[4], b0[4], b1[4];
            ldsm4(a0, ab + offA + (kk << 1));
            ldsm4(a1, ab + offA + ((16 * SSTR + kk) << 1));
            ldsm4(b0, bb + offB + (kk << 1));
            ldsm4(b1, bb + offB + ((kk + 8) << 1));
            #pragma unroll
            for (int nf = 0; nf < 4; nf++) {
                uint32_t bfrag[2] = {b0[nf], b1[nf]};
                mma_f16(acc[0][nf], a0, bfrag);
                mma_f16(acc[1][nf], a1, bfrag);
            }
        }
        __syncthreads();
        buf++;
        if (buf == 3) buf = 0;
    }

    if (bn < split) {
        #pragma unroll
        for (int mf = 0; mf < 2; mf++) {
            int r0 = bm + warpM * 32 + mf * 16 + g;
            float d1a = 0.f, d2a = 0.f, d1b = 0.f, d2b = 0.f;
            #pragma unroll
            for (int nf = 0; nf < 4; nf++) {
                int col = bn + warpN * 32 + nf * 8 + t * 2;
                float bx = 0.f, by = 0.f;
                if (bias) { bx = bias[col]; by = bias[col + 1]; }
                float v0 = acc[mf][nf][0] + bx, v1 = acc[mf][nf][1] + by;
                float v2 = acc[mf][nf][2] + bx, v3 = acc[mf][nf][3] + by;
                if (act) {
                    v0 = lrelu(v0, 0.01f); v1 = lrelu(v1, 0.01f);
                    v2 = lrelu(v2, 0.01f); v3 = lrelu(v3, 0.01f);
                }
                if (r0 < M)
                    store2(C + (size_t)r0 * cld + col, v0, v1);
                if (r0 + 8 < M)
                    store2(C + (size_t)(r0 + 8) * cld + col, v2, v3);
                if (dv1) {
                    float w1 = dv1[col], w1b = dv1[col + 1];
                    float w2 = dv2[col], w2b = dv2[col + 1];
                    d1a += v0 * w1 + v1 * w1b;
                    d2a += v0 * w2 + v1 * w2b;
                    d1b += v2 * w1 + v3 * w1b;
                    d2b += v2 * w2 + v3 * w2b;
                }
            }
            if (dv1) {
                #pragma unroll
                for (int o = 1; o <= 2; o <<= 1) {
                    d1a += __shfl_xor_sync(0xffffffffu, d1a, o);
                    d2a += __shfl_xor_sync(0xffffffffu, d2a, o);
                    d1b += __shfl_xor_sync(0xffffffffu, d1b, o);
                    d2b += __shfl_xor_sync(0xffffffffu, d2b, o);
                }
                if (t == 0) {
                    if (r0 < M) {
                        atomicAdd(dout1 + r0, d1a);
                        atomicAdd(dout2 + r0, d2a);
                    }
                    if (r0 + 8 < M) {
                        atomicAdd(dout1 + r0 + 8, d1b);
                        atomicAdd(dout2 + r0 + 8, d2b);
                    }
                }
            }
        }
    } else {
        int ld2 = Nd - split;
        #pragma unroll
        for (int mf = 0; mf < 2; mf++) {
            int r0 = bm + warpM * 32 + mf * 16 + g;
            #pragma unroll
            for (int nf = 0; nf < 4; nf++) {
                int col = bn + warpN * 32 + nf * 8 + t * 2 - split;
                float bx = bias2[col], by = bias2[col + 1];
                float v0 = acc[mf][nf][0] + bx, v1 = acc[mf][nf][1] + by;
                float v2 = acc[mf][nf][2] + bx, v3 = acc[mf][nf][3] + by;
                if (r0 < M)
                    store2(C2 + (size_t)r0 * ld2 + col, v0, v1);
                if (r0 + 8 < M)
                    store2(C2 + (size_t)(r0 + 8) * ld2 + col, v2, v3);
            }
        }
    }
}

// ---------------------------------------------------------------------------
__device__ __forceinline__ void unpack8(int4 raw, float f[8])
{
    const __half2* hp = reinterpret_cast<const __half2*>(&raw);
    #pragma unroll
    for (int r = 0; r < 4; r++) {
        float2 v = __half22float2(hp[r]);
        f[2 * r] = v.x;
        f[2 * r + 1] = v.y;
    }
}

// ---------------------------------------------------------------------------
// Aggregate: warp per node, 4 edge-groups of 8 lanes, 2-edge-unrolled online
// softmax, shuffle merge. Optional fused dot of OUTPUT row; optional zeroing
// of recycled score buffer.
// ---------------------------------------------------------------------------
template<int D>
__global__ void aggregate_kernel(const __half* __restrict__ feat,
                                 const float* __restrict__ bias,
                                 __half* __restrict__ out,
                                 int N, int act,
                                 const float* __restrict__ ssrc,
                                 const float* __restrict__ sdst,
                                 const float* __restrict__ dv1,
                                 const float* __restrict__ dv2,
                                 float* __restrict__ dout1,
                                 float* __restrict__ dout2,
                                 float* __restrict__ zb1,
                                 float* __restrict__ zb2)
{
    constexpr int V = D / 8;
    constexpr int NI4 = V / 8;
    int warp = (blockIdx.x * blockDim.x + threadIdx.x) >> 5;
    int lane = threadIdx.x & 31;
    int grp = lane >> 3, gl = lane & 7;
    if (warp >= N) return;

    if (zb1 && lane == 0) {
        zb1[warp] = 0.f;
        zb2[warp] = 0.f;
    }

    int beg = g_rowptr[warp];
    int end = g_rowptr[warp + 1];
    float sd = sdst[warp];

    float m = -1e30f;
    float s = 0.f;
    float acc[V];
    #pragma unroll
    for (int v = 0; v < V; v++) acc[v] = 0.f;

    int j = beg + grp;
    while (j + 4 < end) {
        int s0 = g_colsrc[j];
        int s1 = g_colsrc[j + 4];
        float a0 = lrelu(ssrc[s0] + sd, 0.2f);
        float a1 = lrelu(ssrc[s1] + sd, 0.2f);
        float mx = fmaxf(a0, a1);
        if (mx > m) {
            float f = __expf(m - mx);
            s *= f;
            #pragma unroll
            for (int v = 0; v < V; v++) acc[v] *= f;
            m = mx;
        }
        float w0 = __expf(a0 - m);
        float w1 = __expf(a1 - m);
        s += w0 + w1;
        const int4* fr0 = reinterpret_cast<const int4*>(feat + (size_t)s0 * D + gl * V);
        const int4* fr1 = reinterpret_cast<const int4*>(feat + (size_t)s1 * D + gl * V);
        #pragma unroll
        for (int q = 0; q < NI4; q++) {
            int4 r0 = fr0[q];
            int4 r1 = fr1[q];
            float f0[8], f1[8];
            unpack8(r0, f0);
            unpack8(r1, f1);
            #pragma unroll
            for (int r = 0; r < 8; r++)
                acc[q * 8 + r] += w0 * f0[r] + w1 * f1[r];
        }
        j += 8;
    }
    if (j < end) {
        int s0 = g_colsrc[j];
        float a0 = lrelu(ssrc[s0] + sd, 0.2f);
        if (a0 > m) {
            float f = __expf(m - a0);
            s *= f;
            #pragma unroll
            for (int v = 0; v < V; v++) acc[v] *= f;
            m = a0;
        }
        float w0 = __expf(a0 - m);
        s += w0;
        const int4* fr0 = reinterpret_cast<const int4*>(feat + (size_t)s0 * D + gl * V);
        #pragma unroll
        for (int q = 0; q < NI4; q++) {
            float f0[8];
            unpack8(fr0[q], f0);
            #pragma unroll
            for (int r = 0; r < 8; r++)
                acc[q * 8 + r] += w0 * f0[r];
        }
    }

    #pragma unroll
    for (int off = 8; off <= 16; off <<= 1) {
        float m2 = __shfl_xor_sync(0xffffffffu, m, off);
        float s2 = __shfl_xor_sync(0xffffffffu, s, off);
        float mn = fmaxf(m, m2);
        float f1 = __expf(m - mn);
        float f2 = __expf(m2 - mn);
        s = s * f1 + s2 * f2;
        #pragma unroll
        for (int v = 0; v < V; v++) {
            float o = __shfl_xor_sync(0xffffffffu, acc[v], off);
            acc[v] = acc[v] * f1 + o * f2;
        }
        m = mn;
    }

    float inv = 1.f / (s + 1e-16f);
    float d1 = 0.f, d2 = 0.f;
    if (grp == 0) {
        __half* orow = out + (size_t)warp * D + gl * V;
        #pragma unroll
        for (int q = 0; q < NI4; q++) {
            int4 raw;
            __half2* hp = reinterpret_cast<__half2*>(&raw);
            #pragma unroll
            for (int r = 0; r < 4; r++) {
                int d = gl * V + q * 8 + 2 * r;
                float v0 = acc[q * 8 + 2 * r] * inv;
                float v1 = acc[q * 8 + 2 * r + 1] * inv;
                if (bias) { v0 += bias[d]; v1 += bias[d + 1]; }
                if (act) { v0 = lrelu(v0, 0.01f); v1 = lrelu(v1, 0.01f); }
                hp[r] = __floats2half2_rn(v0, v1);
                if (dv1) {
                    d1 += v0 * dv1[d] + v1 * dv1[d + 1];
                    d2 += v0 * dv2[d] + v1 * dv2[d + 1];
                }
            }
            *reinterpret_cast<int4*>(orow + q * 8) = raw;
        }
    }
    if (dv1) {
        #pragma unroll
        for (int o = 4; o > 0; o >>= 1) {
            d1 += __shfl_xor_sync(0xffffffffu, d1, o);
            d2 += __shfl_xor_sync(0xffffffffu, d2, o);
        }
        if (grp == 0 && gl == 0) {
            dout1[warp] = d1;
            dout2[warp] = d2;
        }
    }
}

// ---------------------------------------------------------------------------
__global__ void inner_kernel(float* __restrict__ out, int E)
{
    int warp = (blockIdx.x * blockDim.x + threadIdx.x) >> 5;
    int lane = threadIdx.x & 31;
    int grp = lane >> 3, gl = lane & 7;
    int e = warp * 4 + grp;
    bool valid = e < E;

    float acc = 0.f;
    if (valid) {
        int s = g_src[e];
        int d = g_dst[e];
        int4 a4 = *reinterpret_cast<const int4*>(g_aprim16 + (size_t)s * 64 + gl * 8);
        int4 b4 = *reinterpret_cast<const int4*>(g_aprim16 + (size_t)d * 64 + gl * 8);
        float fa[8], fb[8];
        unpack8(a4, fa);
        unpack8(b4, fb);
        #pragma unroll
        for (int r = 0; r < 8; r++)
            acc += fa[r] * fb[r];
    }
    #pragma unroll
    for (int o = 4; o > 0; o >>= 1)
        acc += __shfl_xor_sync(0xffffffffu, acc, o);
    if (valid && gl == 0)
        out[e] = 1.f / (1.f + expf(-acc));
}

// ---------------------------------------------------------------------------
static void launch_aggregate(const __half* feat, const float* bias, __half* out,
                             int N, int D, int act,
                             const float* ssrc, const float* sdst,
                             const float* dv1, const float* dv2,
                             float* dout1, float* dout2,
                             float* zb1, float* zb2,
                             int wgrid, int TB)
{
    switch (D) {
        case 64:  aggregate_kernel<64> <<<wgrid, TB>>>(feat, bias, out, N, act, ssrc, sdst, dv1, dv2, dout1, dout2, zb1, zb2); break;
        case 128: aggregate_kernel<128><<<wgrid, TB>>>(feat, bias, out, N, act, ssrc, sdst, dv1, dv2, dout1, dout2, zb1, zb2); break;
        case 192: aggregate_kernel<192><<<wgrid, TB>>>(feat, bias, out, N, act, ssrc, sdst, dv1, dv2, dout1, dout2, zb1, zb2); break;
        default:  break;
    }
}

extern "C" void kernel_launch(void* const* d_in, const int* in_sizes, int n_in,
                              void* d_out, int out_size)
{
    const float* z   = (const float*)d_in[0];
    const void*  ei  = d_in[1];
    const float* W1  = (const float*)d_in[2];
    const float* as1 = (const float*)d_in[3];
    const float* ad1 = (const float*)d_in[4];
    const float* b1  = (const float*)d_in[5];
    const float* W2  = (const float*)d_in[6];
    const float* as2 = (const float*)d_in[7];
    const float* ad2 = (const float*)d_in[8];
    const float* b2  = (const float*)d_in[9];
    const float* W3  = (const float*)d_in[10];
    const float* as3 = (const float*)d_in[11];
    const float* ad3 = (const float*)d_in[12];
    const float* b3  = (const float*)d_in[13];
    const float* W4  = (const float*)d_in[14];
    const float* as4 = (const float*)d_in[15];
    const float* ad4 = (const float*)d_in[16];
    const float* b4  = (const float*)d_in[17];
    const float* Wz  = (const float*)d_in[18];
    const float* bz  = (const float*)d_in[19];
    const float* Wa  = (const float*)d_in[20];
    const float* ba  = (const float*)d_in[21];

    int N = in_sizes[0] / 128;
    if (N > MAX_N) N = MAX_N;
    int E = in_sizes[1] / 2;
    if (E > MAX_E) E = MAX_E;

    float* out_z     = (float*)d_out;
    float* out_inner = (float*)d_out + (size_t)N * 128;

    __half* ha;  cudaGetSymbolAddress((void**)&ha, g_h16a);
    __half* hb;  cudaGetSymbolAddress((void**)&hb, g_h16b);
    __half* ap;  cudaGetSymbolAddress((void**)&ap, g_aprim16);
    __half* wt;  cudaGetSymbolAddress((void**)&wt, g_wt);
    float* ws;   cudaGetSymbolAddress((void**)&ws, g_ws);
    float* wd;   cudaGetSymbolAddress((void**)&wd, g_wd);
    float* s1;   cudaGetSymbolAddress((void**)&s1, g_ssrc);
    float* sd1;  cudaGetSymbolAddress((void**)&sd1, g_sdst);
    float* s2;   cudaGetSymbolAddress((void**)&s2, g_ssrc2);
    float* sd2;  cudaGetSymbolAddress((void**)&sd2, g_sdst2);

    const int TB = 256;
    int egrid = (E + TB - 1) / TB;
    int wgrid = (N * 32 + TB - 1) / TB;
    int iegrid = (((E + 3) / 4) * 32 + TB - 1) / TB;
    int nblk = (N + 1023) / 1024;
    int setup_items = N * 32 + 139264 + 384 * 32 + 3 * N + 64;
    int sgrid = (setup_items + TB - 1) / TB;
    int mt = (N + 127) / 128;
    const int NS = 1 << 30;

    detect_dtype_kernel<<<1, 256>>>((const int*)ei);
    setup_kernel<<<sgrid, TB>>>(z, W1, W2, W3, W4, Wz, Wa,
                                as2, ad2, as3, ad3, as4, ad4, hb, wt, N);
    convert_hist_kernel<<<egrid, TB>>>(ei, E);
    // L1 GEMM with fused L1 dots -> buffer A
    {
        dim3 grid(1, mt);
        gemm_fp16_kernel<__half><<<grid, 256>>>(hb, wt + WT1_OFF, nullptr, ha,
                                                N, 128, 64, 0, 64, nullptr, nullptr, NS,
                                                as1, ad1, s1, sd1);
    }
    scan_fused_kernel<<<nblk, 1024>>>(N, nblk);
    scatter_kernel<<<egrid, TB>>>(E);

    // Layer 1 aggregate: ha -> hb; reads buf A, fused L2 dots -> buf B
    launch_aggregate(ha, b1, hb, N, 64, 1, s1, sd1, ws, wd, s2, sd2,
                     nullptr, nullptr, wgrid, TB);

    // Layer 2: aggregate(hb, buf B) -> ha (zeroes buf A); gemm -> hb with
    // fused L3 dots -> buf A
    launch_aggregate(hb, nullptr, ha, N, 64, 0, s2, sd2, nullptr, nullptr,
                     nullptr, nullptr, s1, sd1, wgrid, TB);
    {
        dim3 grid(2, mt);
        gemm_fp16_kernel<__half><<<grid, 256>>>(ha, wt + WT2_OFF, b2, hb,
                                                N, 64, 128, 1, 128, nullptr, nullptr, NS,
                                                ws + 64, wd + 64, s1, sd1);
    }
    // Layer 3: aggregate(hb, buf A) -> ha (zeroes buf B); gemm -> hb with
    // fused L4 dots -> buf B
    launch_aggregate(hb, nullptr, ha, N, 128, 0, s1, sd1, nullptr, nullptr,
                     nullptr, nullptr, s2, sd2, wgrid, TB);
    {
        dim3 grid(3, mt);
        gemm_fp16_kernel<__half><<<grid, 256>>>(ha, wt + WT3_OFF, b3, hb,
                                                N, 128, 192, 1, 192, nullptr, nullptr, NS,
                                                ws + 192, wd + 192, s2, sd2);
    }
    // Layer 4: aggregate(hb, buf B) -> ha; gemm -> hb
    launch_aggregate(hb, nullptr, ha, N, 192, 0, s2, sd2, nullptr, nullptr,
                     nullptr, nullptr, nullptr, nullptr, wgrid, TB);
    {
        dim3 grid(4, mt);
        gemm_fp16_kernel<__half><<<grid, 256>>>(ha, wt + WT4_OFF, b4, hb,
                                                N, 192, 256, 1, 256, nullptr, nullptr, NS,
                                                nullptr, nullptr, nullptr, nullptr);
    }

    // merged heads
    {
        dim3 grid(3, mt);
        gemm_fp16_kernel<float><<<grid, 256>>>(hb, wt + WTZ_OFF, bz, out_z,
                                               N, 256, 192, 0, 128, ba, ap, 128,
                                               nullptr, nullptr, nullptr, nullptr);
    }
    inner_kernel<<<iegrid, TB>>>(out_inner, E);
}